// round 2
// baseline (speedup 1.0000x reference)
#include <cuda_runtime.h>
#include <cuda_bf16.h>
#include <math.h>

// Problem constants
#define BATCH   32768
#define DDIM    1024
#define H1DIM   512
#define H2DIM   512
#define INDIM   2049          // 2*D + 1
#define KPAD    2056          // INDIM padded up to multiple of 8 (and 4-float alignment)
#define QDEG    4             // Q
#define RHO_F   0.99f

// ---------------- device scratch (no allocations allowed) ----------------
__device__ float g_inp[BATCH * KPAD];     // concat(x, loss, grad) padded  (~269 MB)
__device__ float g_W1p[KPAD * H1DIM];     // W1 zero-padded to KPAD rows   (~4.2 MB)
__device__ float g_h1[BATCH * H1DIM];     // layer-1 activations           (64 MB)
__device__ float g_h2[BATCH * H2DIM];     // layer-2 activations           (64 MB)

// ---------------- prep kernels ----------------
__global__ void concat_kernel(const float* __restrict__ x,
                              const float* __restrict__ loss,
                              const float* __restrict__ grad) {
    int i = blockIdx.x * blockDim.x + threadIdx.x;
    const int total = BATCH * KPAD;
    if (i >= total) return;
    int r = i / KPAD;
    int c = i - r * KPAD;
    float v;
    if (c < DDIM)              v = x[r * DDIM + c];
    else if (c == DDIM)        v = loss[r];
    else if (c < INDIM)        v = grad[r * DDIM + (c - DDIM - 1)];
    else                       v = 0.0f;
    g_inp[i] = v;
}

__global__ void padw1_kernel(const float* __restrict__ W1) {
    int i = blockIdx.x * blockDim.x + threadIdx.x;
    const int total = KPAD * H1DIM;
    if (i >= total) return;
    int r = i / H1DIM;
    int c = i - r * H1DIM;
    g_W1p[i] = (r < INDIM) ? W1[r * H1DIM + c] : 0.0f;
}

// ---------------- SGEMM: C(MxN) = act( A(MxK) @ B(KxN) + bias ) ----------------
// A row-major stride K, B row-major stride N. M%128==0, N%128==0, K%8==0 assumed.
#define BM 128
#define BN 128
#define BK 8
#define TM 8
#define TN 8

// ACT: 0 = relu(acc + bias),  1 = scale * tanh(acc + bias)
template <int ACT>
__global__ void __launch_bounds__(256, 2)
sgemm_kernel(const float* __restrict__ A, const float* __restrict__ B,
             const float* __restrict__ bias, float* __restrict__ C,
             int M, int N, int K,
             const float* __restrict__ alpha_raw, const int* __restrict__ t_ptr) {
    __shared__ float As[BK][BM];
    __shared__ float Bs[BK][BN];

    const int tid = threadIdx.x;
    const int bm = blockIdx.y * BM;
    const int bn = blockIdx.x * BN;
    const int tr = (tid >> 4) * TM;   // 0..120
    const int tc = (tid & 15) * TN;   // 0..120

    // A-tile loader mapping: 128 rows x 8 k, float4 along K (2 loaders/row)
    const int aRow = tid >> 1;          // 0..127
    const int aCol = (tid & 1) * 4;     // 0 or 4
    // B-tile loader mapping: 8 k-rows x 128 n, float4 along N
    const int bRow = tid >> 5;          // 0..7
    const int bCol = (tid & 31) * 4;    // 0..124

    const float* Aptr = A + (size_t)(bm + aRow) * K + aCol;
    const float* Bptr = B + (size_t)bRow * N + bn + bCol;

    float acc[TM][TN];
#pragma unroll
    for (int i = 0; i < TM; i++)
#pragma unroll
        for (int j = 0; j < TN; j++) acc[i][j] = 0.0f;

    for (int k0 = 0; k0 < K; k0 += BK) {
        float4 av = *(const float4*)(Aptr + k0);
        As[aCol + 0][aRow] = av.x;
        As[aCol + 1][aRow] = av.y;
        As[aCol + 2][aRow] = av.z;
        As[aCol + 3][aRow] = av.w;
        float4 bv = *(const float4*)(Bptr + (size_t)k0 * N);
        *(float4*)&Bs[bRow][bCol] = bv;
        __syncthreads();

#pragma unroll
        for (int kk = 0; kk < BK; kk++) {
            float a[TM], b[TN];
            *(float4*)&a[0] = *(const float4*)&As[kk][tr];
            *(float4*)&a[4] = *(const float4*)&As[kk][tr + 4];
            *(float4*)&b[0] = *(const float4*)&Bs[kk][tc];
            *(float4*)&b[4] = *(const float4*)&Bs[kk][tc + 4];
#pragma unroll
            for (int i = 0; i < TM; i++)
#pragma unroll
                for (int j = 0; j < TN; j++)
                    acc[i][j] = fmaf(a[i], b[j], acc[i][j]);
        }
        __syncthreads();
    }

    // epilogue scalar for the output layer
    float scale = 1.0f;
    if (ACT == 1) {
        int ti = *t_ptr;
        // t may arrive as int32 (expected) or float32; small ints disambiguate.
        float tf = (ti >= 0 && ti < 1000000) ? (float)ti : __int_as_float(ti);
        float poly = 0.0f, tp = 1.0f;
#pragma unroll
        for (int q = 0; q <= QDEG; q++) {
            float a = alpha_raw[q];
            float sp = (a > 20.0f) ? a : log1pf(expf(a));  // softplus
            poly = fmaf(sp, tp, poly);
            tp *= tf;
        }
        scale = poly * powf(RHO_F, tf);
    }

#pragma unroll
    for (int i = 0; i < TM; i++) {
        const int row = bm + tr + i;
        float out[TN];
#pragma unroll
        for (int j = 0; j < TN; j++) {
            float v = acc[i][j] + bias[bn + tc + j];
            if (ACT == 0) v = fmaxf(v, 0.0f);
            else          v = scale * tanhf(v);
            out[j] = v;
        }
        float* Crow = C + (size_t)row * N + bn + tc;
        *(float4*)(Crow + 0) = *(const float4*)&out[0];
        *(float4*)(Crow + 4) = *(const float4*)&out[4];
    }
}

// ---------------- launch ----------------
extern "C" void kernel_launch(void* const* d_in, const int* in_sizes, int n_in,
                              void* d_out, int out_size) {
    const float* x      = (const float*)d_in[0];
    const float* loss   = (const float*)d_in[1];
    const float* grad   = (const float*)d_in[2];
    const float* W1     = (const float*)d_in[3];
    const float* b1     = (const float*)d_in[4];
    const float* W2     = (const float*)d_in[5];
    const float* b2     = (const float*)d_in[6];
    const float* W3     = (const float*)d_in[7];
    const float* b3     = (const float*)d_in[8];
    const float* alpha  = (const float*)d_in[9];
    const int*   t_ptr  = (const int*)d_in[10];
    float* out = (float*)d_out;

    float* inp = nullptr; float* w1p = nullptr; float* h1 = nullptr; float* h2 = nullptr;
    cudaGetSymbolAddress((void**)&inp, g_inp);
    cudaGetSymbolAddress((void**)&w1p, g_W1p);
    cudaGetSymbolAddress((void**)&h1,  g_h1);
    cudaGetSymbolAddress((void**)&h2,  g_h2);

    // 1) build padded concat input + padded W1
    {
        int total = BATCH * KPAD;
        concat_kernel<<<(total + 255) / 256, 256>>>(x, loss, grad);
        int totw = KPAD * H1DIM;
        padw1_kernel<<<(totw + 255) / 256, 256>>>(W1);
    }

    // 2) layer 1: (32768 x 2056) @ (2056 x 512) -> relu -> h1
    {
        dim3 grid(H1DIM / BN, BATCH / BM);
        sgemm_kernel<0><<<grid, 256>>>(inp, w1p, b1, h1,
                                       BATCH, H1DIM, KPAD, nullptr, nullptr);
    }
    // 3) layer 2: (32768 x 512) @ (512 x 512) -> relu -> h2
    {
        dim3 grid(H2DIM / BN, BATCH / BM);
        sgemm_kernel<0><<<grid, 256>>>(h1, W2, b2, h2,
                                       BATCH, H2DIM, H1DIM, nullptr, nullptr);
    }
    // 4) layer 3: (32768 x 512) @ (512 x 1024) -> scale * tanh -> out
    {
        dim3 grid(DDIM / BN, BATCH / BM);
        sgemm_kernel<1><<<grid, 256>>>(h2, W3, b3, out,
                                       BATCH, DDIM, H2DIM, alpha, t_ptr);
    }
}

// round 3
// speedup vs baseline: 4.3464x; 4.3464x over previous
#include <cuda_runtime.h>
#include <cuda_bf16.h>
#include <math.h>

// Problem constants
#define BATCH   32768
#define DDIM    1024
#define H1DIM   512
#define H2DIM   512
#define INDIM   2049
#define KPAD    2080          // INDIM padded to a multiple of 32
#define QDEG    4
#define RHO_F   0.99f

// ---------------- device scratch (no allocations allowed) ----------------
__device__ float g_inp[BATCH * KPAD];     // concat(x, loss, grad), tf32-rounded (~272 MB)
__device__ float g_W1p[KPAD * H1DIM];     // W1 zero-padded + tf32-rounded
__device__ float g_W2r[H1DIM * H2DIM];    // W2 tf32-rounded
__device__ float g_W3r[H2DIM * DDIM];     // W3 tf32-rounded
__device__ float g_h1[BATCH * H1DIM];     // layer-1 activations (tf32-rounded)
__device__ float g_h2[BATCH * H2DIM];     // layer-2 activations (tf32-rounded)

// ---------------- helpers ----------------
__device__ __forceinline__ float tf32r(float x) {
    float r;
    asm("cvt.rna.tf32.f32 %0, %1;" : "=f"(r) : "f"(x));
    return r;
}

__device__ __forceinline__ void cpasync16(void* smem_dst, const void* gmem_src) {
    unsigned s = (unsigned)__cvta_generic_to_shared(smem_dst);
    asm volatile("cp.async.cg.shared.global [%0], [%1], 16;\n" :: "r"(s), "l"(gmem_src));
}

__device__ __forceinline__ void mma_tf32(float* d, const float* a, const float* b) {
    asm volatile(
        "mma.sync.aligned.m16n8k8.row.col.f32.tf32.tf32.f32 "
        "{%0,%1,%2,%3}, {%4,%5,%6,%7}, {%8,%9}, {%0,%1,%2,%3};\n"
        : "+f"(d[0]), "+f"(d[1]), "+f"(d[2]), "+f"(d[3])
        : "r"(__float_as_uint(a[0])), "r"(__float_as_uint(a[1])),
          "r"(__float_as_uint(a[2])), "r"(__float_as_uint(a[3])),
          "r"(__float_as_uint(b[0])), "r"(__float_as_uint(b[1])));
}

// ---------------- prep kernels ----------------
__global__ void concat_kernel(const float* __restrict__ x,
                              const float* __restrict__ loss,
                              const float* __restrict__ grad) {
    int i = blockIdx.x * blockDim.x + threadIdx.x;
    const int total = BATCH * KPAD;
    if (i >= total) return;
    int r = i / KPAD;
    int c = i - r * KPAD;
    float v;
    if (c < DDIM)              v = x[r * DDIM + c];
    else if (c == DDIM)        v = loss[r];
    else if (c < INDIM)        v = grad[r * DDIM + (c - DDIM - 1)];
    else                       v = 0.0f;
    g_inp[i] = tf32r(v);
}

__global__ void padw1_kernel(const float* __restrict__ W1) {
    int i = blockIdx.x * blockDim.x + threadIdx.x;
    const int total = KPAD * H1DIM;
    if (i >= total) return;
    int r = i / H1DIM;
    int c = i - r * H1DIM;
    g_W1p[i] = (r < INDIM) ? tf32r(W1[r * H1DIM + c]) : 0.0f;
}

__global__ void roundw_kernel(const float* __restrict__ W, float* __restrict__ Wo, int n) {
    int i = blockIdx.x * blockDim.x + threadIdx.x;
    if (i < n) Wo[i] = tf32r(W[i]);
}

// ---------------- TF32 MMA GEMM ----------------
// C(MxN) = act( A(MxK) @ B(KxN) + bias ).  A,B row-major, tf32-prerounded.
// M%128==0, N%128==0, K%16==0.
#define BM 128
#define BN 128
#define BK 16
#define ASTR 20    // BK + 4 pad: bank(a0)=(4g+t) -> conflict-free fragment loads
#define BSTR 136   // BN + 8 pad: bank(b0)=(8k+n) -> conflict-free fragment loads

// ACT: 0 = relu(acc+bias), tf32-rounded output;  1 = scale * tanh(acc+bias)
template <int ACT>
__global__ void __launch_bounds__(256, 2)
mma_gemm(const float* __restrict__ A, const float* __restrict__ B,
         const float* __restrict__ bias, float* __restrict__ C,
         int M, int N, int K,
         const float* __restrict__ alpha_raw, const int* __restrict__ t_ptr) {
    __shared__ float As[2][BM * ASTR];
    __shared__ float Bs[2][BK * BSTR];

    const int tid  = threadIdx.x;
    const int wid  = tid >> 5;
    const int lane = tid & 31;
    const int g    = lane >> 2;   // groupID (0..7)
    const int tg   = lane & 3;    // thread-in-group (0..3)
    const int warp_m = (wid >> 2) * 64;   // 0 or 64
    const int warp_n = (wid & 3) * 32;    // 0,32,64,96
    const int bm = blockIdx.y * BM;
    const int bn = blockIdx.x * BN;

    // cp.async mappings (each thread copies 2x16B for A and 2x16B for B per stage)
    const int arow = tid >> 1;            // 0..127
    const int acol = (tid & 1) * 8;       // 0 or 8 (floats)
    const int brow = tid >> 4;            // 0..15
    const int bcol = (tid & 15) * 8;      // 0..120 (floats)

    const float* Ag = A + (size_t)(bm + arow) * K + acol;
    const float* Bg = B + (size_t)brow * N + bn + bcol;

    float acc[4][4][4];
#pragma unroll
    for (int i = 0; i < 4; i++)
#pragma unroll
        for (int j = 0; j < 4; j++)
#pragma unroll
            for (int q = 0; q < 4; q++) acc[i][j][q] = 0.0f;

    const int nst = K / BK;

    // prologue: stage 0
    {
        float* ad = &As[0][arow * ASTR + acol];
        float* bd = &Bs[0][brow * BSTR + bcol];
        cpasync16(ad,     Ag);
        cpasync16(ad + 4, Ag + 4);
        cpasync16(bd,     Bg);
        cpasync16(bd + 4, Bg + 4);
        asm volatile("cp.async.commit_group;\n");
    }

    for (int kt = 0; kt < nst; kt++) {
        if (kt + 1 < nst) {
            const int nb = (kt + 1) & 1;
            const int k0 = (kt + 1) * BK;
            float* ad = &As[nb][arow * ASTR + acol];
            float* bd = &Bs[nb][brow * BSTR + bcol];
            cpasync16(ad,     Ag + k0);
            cpasync16(ad + 4, Ag + k0 + 4);
            cpasync16(bd,     Bg + (size_t)k0 * N);
            cpasync16(bd + 4, Bg + (size_t)k0 * N + 4);
            asm volatile("cp.async.commit_group;\n");
            asm volatile("cp.async.wait_group 1;\n");
        } else {
            asm volatile("cp.async.wait_group 0;\n");
        }
        __syncthreads();

        const int buf = kt & 1;
        const float* as = &As[buf][0];
        const float* bs = &Bs[buf][0];
#pragma unroll
        for (int ks = 0; ks < BK; ks += 8) {
            float a[4][4];
#pragma unroll
            for (int i = 0; i < 4; i++) {
                const int r0 = warp_m + i * 16 + g;
                a[i][0] = as[(r0)     * ASTR + ks + tg];
                a[i][1] = as[(r0 + 8) * ASTR + ks + tg];
                a[i][2] = as[(r0)     * ASTR + ks + tg + 4];
                a[i][3] = as[(r0 + 8) * ASTR + ks + tg + 4];
            }
            float b[4][2];
#pragma unroll
            for (int j = 0; j < 4; j++) {
                const int c0 = warp_n + j * 8 + g;
                b[j][0] = bs[(ks + tg)     * BSTR + c0];
                b[j][1] = bs[(ks + tg + 4) * BSTR + c0];
            }
#pragma unroll
            for (int i = 0; i < 4; i++)
#pragma unroll
                for (int j = 0; j < 4; j++)
                    mma_tf32(acc[i][j], a[i], b[j]);
        }
        __syncthreads();
    }

    // epilogue scalar for the output layer
    float scale = 1.0f;
    if (ACT == 1) {
        int ti = *t_ptr;
        float tf = (ti >= 0 && ti < 1000000) ? (float)ti : __int_as_float(ti);
        float poly = 0.0f, tp = 1.0f;
#pragma unroll
        for (int q = 0; q <= QDEG; q++) {
            float av = alpha_raw[q];
            float sp = (av > 20.0f) ? av : log1pf(expf(av));
            poly = fmaf(sp, tp, poly);
            tp *= tf;
        }
        scale = poly * powf(RHO_F, tf);
    }

#pragma unroll
    for (int i = 0; i < 4; i++) {
#pragma unroll
        for (int j = 0; j < 4; j++) {
            const int row = bm + warp_m + i * 16 + g;
            const int col = bn + warp_n + j * 8 + tg * 2;
            const float bz0 = bias[col];
            const float bz1 = bias[col + 1];
            float v0 = acc[i][j][0] + bz0;
            float v1 = acc[i][j][1] + bz1;
            float v2 = acc[i][j][2] + bz0;
            float v3 = acc[i][j][3] + bz1;
            if (ACT == 0) {
                v0 = tf32r(fmaxf(v0, 0.0f));
                v1 = tf32r(fmaxf(v1, 0.0f));
                v2 = tf32r(fmaxf(v2, 0.0f));
                v3 = tf32r(fmaxf(v3, 0.0f));
            } else {
                v0 = scale * tanhf(v0);
                v1 = scale * tanhf(v1);
                v2 = scale * tanhf(v2);
                v3 = scale * tanhf(v3);
            }
            float2 p0 = make_float2(v0, v1);
            float2 p1 = make_float2(v2, v3);
            *(float2*)(C + (size_t)row * N + col)       = p0;
            *(float2*)(C + (size_t)(row + 8) * N + col) = p1;
        }
    }
}

// ---------------- launch ----------------
extern "C" void kernel_launch(void* const* d_in, const int* in_sizes, int n_in,
                              void* d_out, int out_size) {
    const float* x      = (const float*)d_in[0];
    const float* loss   = (const float*)d_in[1];
    const float* grad   = (const float*)d_in[2];
    const float* W1     = (const float*)d_in[3];
    const float* b1     = (const float*)d_in[4];
    const float* W2     = (const float*)d_in[5];
    const float* b2     = (const float*)d_in[6];
    const float* W3     = (const float*)d_in[7];
    const float* b3     = (const float*)d_in[8];
    const float* alpha  = (const float*)d_in[9];
    const int*   t_ptr  = (const int*)d_in[10];
    float* out = (float*)d_out;

    float *inp, *w1p, *w2r, *w3r, *h1, *h2;
    cudaGetSymbolAddress((void**)&inp, g_inp);
    cudaGetSymbolAddress((void**)&w1p, g_W1p);
    cudaGetSymbolAddress((void**)&w2r, g_W2r);
    cudaGetSymbolAddress((void**)&w3r, g_W3r);
    cudaGetSymbolAddress((void**)&h1,  g_h1);
    cudaGetSymbolAddress((void**)&h2,  g_h2);

    // 1) prep: concat + round everything to tf32 (RTN)
    {
        int total = BATCH * KPAD;
        concat_kernel<<<(total + 255) / 256, 256>>>(x, loss, grad);
        int totw = KPAD * H1DIM;
        padw1_kernel<<<(totw + 255) / 256, 256>>>(W1);
        int n2 = H1DIM * H2DIM;
        roundw_kernel<<<(n2 + 255) / 256, 256>>>(W2, w2r, n2);
        int n3 = H2DIM * DDIM;
        roundw_kernel<<<(n3 + 255) / 256, 256>>>(W3, w3r, n3);
    }

    // 2) layer 1: (32768 x 2080) @ (2080 x 512) -> relu -> h1
    {
        dim3 grid(H1DIM / BN, BATCH / BM);
        mma_gemm<0><<<grid, 256>>>(inp, w1p, b1, h1,
                                   BATCH, H1DIM, KPAD, nullptr, nullptr);
    }
    // 3) layer 2: (32768 x 512) @ (512 x 512) -> relu -> h2
    {
        dim3 grid(H2DIM / BN, BATCH / BM);
        mma_gemm<0><<<grid, 256>>>(h1, w2r, b2, h2,
                                   BATCH, H2DIM, H1DIM, nullptr, nullptr);
    }
    // 4) layer 3: (32768 x 512) @ (512 x 1024) -> scale*tanh -> out
    {
        dim3 grid(DDIM / BN, BATCH / BM);
        mma_gemm<1><<<grid, 256>>>(h2, w3r, b3, out,
                                   BATCH, DDIM, H2DIM, alpha, t_ptr);
    }
}

// round 5
// speedup vs baseline: 6.4009x; 1.4727x over previous
#include <cuda_runtime.h>
#include <cuda_bf16.h>
#include <math.h>
#include <stdint.h>

// ---------------- problem constants ----------------
#define BATCH   32768
#define DDIM    1024
#define H1DIM   512
#define H2DIM   512
#define KPAD1   2080          // layer-1 K: [x(1024), grad(1024), loss(1), pad..2080]
#define QDEG    4
#define RHO_F   0.99f

// ---------------- GEMM tiling ----------------
#define BM 128
#define BN 256
#define BK 32
#define ASTR 36               // BK + 4 pad  (bank map 4g+tg: conflict-free)
#define BSTR 264              // BN + 8 pad  (bank map 8tg+g: conflict-free)
#define SA_STAGE (BM * ASTR)  // 4608 floats
#define SB_STAGE (BK * BSTR)  // 8448 floats
#define SMEM_BYTES ((3 * SA_STAGE + 3 * SB_STAGE) * 4)   // 156672

// ---------------- device scratch ----------------
__device__ float g_W1p[KPAD1 * H1DIM];   // W1 row-permuted + zero-padded, tf32-RNA, [K][N]
__device__ float g_W2r[H1DIM * H2DIM];   // tf32-RNA, [K][N]
__device__ float g_W3r[H2DIM * DDIM];    // tf32-RNA, [K][N]
__device__ float g_h1[BATCH * H1DIM];
__device__ float g_h2[BATCH * H2DIM];

// ---------------- helpers ----------------
__device__ __forceinline__ float tf32r(float x) {
    float r; asm("cvt.rna.tf32.f32 %0, %1;" : "=f"(r) : "f"(x)); return r;
}
__device__ __forceinline__ uint32_t smem_u32(const void* p) {
    uint32_t a;
    asm("{ .reg .u64 t; cvta.to.shared.u64 t, %1; cvt.u32.u64 %0, t; }" : "=r"(a) : "l"(p));
    return a;
}
__device__ __forceinline__ void cpasync16(uint32_t saddr, const void* g) {
    asm volatile("cp.async.cg.shared.global [%0], [%1], 16;" :: "r"(saddr), "l"(g));
}
__device__ __forceinline__ void mma_tf32(float* d, const float* a, const float* b) {
    asm volatile(
        "mma.sync.aligned.m16n8k8.row.col.f32.tf32.tf32.f32 "
        "{%0,%1,%2,%3}, {%4,%5,%6,%7}, {%8,%9}, {%0,%1,%2,%3};\n"
        : "+f"(d[0]), "+f"(d[1]), "+f"(d[2]), "+f"(d[3])
        : "r"(__float_as_uint(a[0])), "r"(__float_as_uint(a[1])),
          "r"(__float_as_uint(a[2])), "r"(__float_as_uint(a[3])),
          "r"(__float_as_uint(b[0])), "r"(__float_as_uint(b[1])));
}

// ---------------- prep kernels (tiny) ----------------
// W1 row-permuted to match A column order [x, grad, loss]:
//   k<1024 -> W1 row k ; 1024..2047 -> W1 row k+1 (grad) ; 2048 -> W1 row 1024 (loss) ; else 0
__global__ void prep_w1(const float* __restrict__ W1) {
    int i = blockIdx.x * blockDim.x + threadIdx.x;
    if (i >= KPAD1 * H1DIM) return;
    int k = i / H1DIM;
    int n = i - k * H1DIM;
    float v = 0.0f;
    if (k < 1024)       v = W1[(size_t)k * H1DIM + n];
    else if (k < 2048)  v = W1[(size_t)(k + 1) * H1DIM + n];
    else if (k == 2048) v = W1[(size_t)1024 * H1DIM + n];
    g_W1p[i] = tf32r(v);
}
__global__ void roundw_kernel(const float* __restrict__ W, float* __restrict__ Wo, int n) {
    int i = blockIdx.x * blockDim.x + threadIdx.x;
    if (i < n) Wo[i] = tf32r(W[i]);
}

// ---------------- TF32 mma.sync GEMM ----------------
// C(MxN) = act( A(MxK) @ B(KxN) + bias ); B tf32-prerounded [K][N].
// AMODE 0: A row-major stride K (tf32-prerounded).
// AMODE 1: layer-1: A streamed from x/grad/loss with on-the-fly RNA rounding, K=KPAD1.
template <int ACT, int AMODE>
__global__ void __launch_bounds__(256, 1)
mma_gemm(const float* __restrict__ A, const float* __restrict__ Agrad,
         const float* __restrict__ Aloss,
         const float* __restrict__ Bw, const float* __restrict__ bias,
         float* __restrict__ C, int M, int N, int K,
         const float* __restrict__ alpha_raw, const int* __restrict__ t_ptr) {
    extern __shared__ float sm[];
    float* Asm = sm;                 // 3 stages x SA_STAGE
    float* Bsm = sm + 3 * SA_STAGE;  // 3 stages x SB_STAGE

    const int tid  = threadIdx.x;
    const int wid  = tid >> 5;
    const int lane = tid & 31;
    const int g    = lane >> 2;
    const int tg   = lane & 3;
    const int warp_m = (wid >> 2) * 64;   // 0 / 64
    const int warp_n = (wid & 3) * 64;    // 0,64,128,192
    const int m0 = blockIdx.y * BM;
    const int n0 = blockIdx.x * BN;
    const int nt = K / BK;

    const uint32_t sA = smem_u32(Asm);
    const uint32_t sB = smem_u32(Bsm);

    float acc[4][8][4];
#pragma unroll
    for (int i = 0; i < 4; i++)
#pragma unroll
        for (int j = 0; j < 8; j++)
#pragma unroll
            for (int q = 0; q < 4; q++) acc[i][j][q] = 0.0f;

    // ---- loaders ----
    auto loadB = [&](int ck, int st) {
        const uint32_t bbase = sB + (uint32_t)(st * SB_STAGE) * 4u;
#pragma unroll
        for (int i = 0; i < 8; i++) {
            int c = tid + 256 * i;
            int kr = c >> 6, c64 = c & 63;
            cpasync16(bbase + (uint32_t)(kr * BSTR + c64 * 4) * 4u,
                      Bw + (size_t)(ck * BK + kr) * N + n0 + c64 * 4);
        }
    };
    auto loadA_ca = [&](int ck, int st) {   // AMODE 0
        const uint32_t abase = sA + (uint32_t)(st * SA_STAGE) * 4u;
#pragma unroll
        for (int i = 0; i < 4; i++) {
            int c = tid + 256 * i;
            int r = c >> 3, c8 = c & 7;
            cpasync16(abase + (uint32_t)(r * ASTR + c8 * 4) * 4u,
                      A + (size_t)(m0 + r) * K + ck * BK + c8 * 4);
        }
    };
    auto ldgA = [&](int ck, float4* v) {    // AMODE 1 gather (non-loss chunks)
#pragma unroll
        for (int i = 0; i < 4; i++) {
            int c = tid + 256 * i;
            int r = c >> 3, c8 = c & 7;
            int col = ck * BK + c8 * 4;
            const float* s = (col < 1024)
                ? (A     + (size_t)(m0 + r) * 1024 + col)
                : (Agrad + (size_t)(m0 + r) * 1024 + (col - 1024));
            v[i] = *(const float4*)s;
        }
    };
    auto stsA = [&](int ck, int st, const float4* v) {   // AMODE 1 store (with rounding)
        float* abase = Asm + st * SA_STAGE;
#pragma unroll
        for (int i = 0; i < 4; i++) {
            int c = tid + 256 * i;
            int r = c >> 3, c8 = c & 7;
            float4 w;
            if (ck == 64) {   // loss/pad chunk (cols 2048..2079)
                w = make_float4(0.0f, 0.0f, 0.0f, 0.0f);
                if (c8 == 0) w.x = tf32r(Aloss[m0 + r]);
            } else {
                w.x = tf32r(v[i].x); w.y = tf32r(v[i].y);
                w.z = tf32r(v[i].z); w.w = tf32r(v[i].w);
            }
            *(float4*)(abase + r * ASTR + c8 * 4) = w;
        }
    };

    // ---- prologue: stages 0, 1 ----
    if (AMODE == 1) {
        float4 v[4];
        ldgA(0, v); stsA(0, 0, v);
        ldgA(1, v); stsA(1, 1, v);
        loadB(0, 0); asm volatile("cp.async.commit_group;" ::: "memory");
        loadB(1, 1); asm volatile("cp.async.commit_group;" ::: "memory");
    } else {
        loadA_ca(0, 0); loadB(0, 0);
        asm volatile("cp.async.commit_group;" ::: "memory");
        loadA_ca(1, 1); loadB(1, 1);
        asm volatile("cp.async.commit_group;" ::: "memory");
    }

    // ---- mainloop ----
    for (int kt = 0; kt < nt; kt++) {
        const int st = kt % 3;
        const bool pf = (kt + 2 < nt);
        if (pf) asm volatile("cp.async.wait_group 1;" ::: "memory");
        else    asm volatile("cp.async.wait_group 0;" ::: "memory");
        __syncthreads();

        float4 vreg[4];
        if (AMODE == 1 && pf && (kt + 2 != 64)) ldgA(kt + 2, vreg);  // hide LDG under MMA

        const float* as = Asm + st * SA_STAGE;
        const float* bs = Bsm + st * SB_STAGE;
#pragma unroll
        for (int ks = 0; ks < BK; ks += 8) {
            float a[4][4], b[8][2];
#pragma unroll
            for (int i = 0; i < 4; i++) {
                const int r0 = warp_m + i * 16 + g;
                a[i][0] = as[r0 * ASTR + ks + tg];
                a[i][1] = as[(r0 + 8) * ASTR + ks + tg];
                a[i][2] = as[r0 * ASTR + ks + tg + 4];
                a[i][3] = as[(r0 + 8) * ASTR + ks + tg + 4];
            }
#pragma unroll
            for (int j = 0; j < 8; j++) {
                const int c0 = warp_n + j * 8 + g;
                b[j][0] = bs[(ks + tg) * BSTR + c0];
                b[j][1] = bs[(ks + tg + 4) * BSTR + c0];
            }
#pragma unroll
            for (int i = 0; i < 4; i++)
#pragma unroll
                for (int j = 0; j < 8; j++)
                    mma_tf32(acc[i][j], a[i], b[j]);
        }

        if (pf) {
            const int sp = (kt + 2) % 3;
            if (AMODE == 1) stsA(kt + 2, sp, vreg);
            else            loadA_ca(kt + 2, sp);
            loadB(kt + 2, sp);
            asm volatile("cp.async.commit_group;" ::: "memory");
        }
    }

    // ---- epilogue ----
    float scale = 1.0f;
    if (ACT == 1) {
        int ti = *t_ptr;
        float tf = (ti >= 0 && ti < 1000000) ? (float)ti : __int_as_float(ti);
        float poly = 0.0f, tp = 1.0f;
#pragma unroll
        for (int q = 0; q <= QDEG; q++) {
            float av = alpha_raw[q];
            float sp = (av > 20.0f) ? av : log1pf(expf(av));
            poly = fmaf(sp, tp, poly);
            tp *= tf;
        }
        scale = poly * powf(RHO_F, tf);
    }

#pragma unroll
    for (int i = 0; i < 4; i++) {
#pragma unroll
        for (int j = 0; j < 8; j++) {
            const int row = m0 + warp_m + i * 16 + g;
            const int col = n0 + warp_n + j * 8 + tg * 2;
            const float bz0 = bias[col];
            const float bz1 = bias[col + 1];
            float v0 = acc[i][j][0] + bz0;
            float v1 = acc[i][j][1] + bz1;
            float v2 = acc[i][j][2] + bz0;
            float v3 = acc[i][j][3] + bz1;
            if (ACT == 0) {
                v0 = tf32r(fmaxf(v0, 0.0f)); v1 = tf32r(fmaxf(v1, 0.0f));
                v2 = tf32r(fmaxf(v2, 0.0f)); v3 = tf32r(fmaxf(v3, 0.0f));
            } else {
                v0 = scale * tanhf(v0); v1 = scale * tanhf(v1);
                v2 = scale * tanhf(v2); v3 = scale * tanhf(v3);
            }
            *(float2*)(C + (size_t)row * N + col)       = make_float2(v0, v1);
            *(float2*)(C + (size_t)(row + 8) * N + col) = make_float2(v2, v3);
        }
    }
}

// ---------------- launch ----------------
extern "C" void kernel_launch(void* const* d_in, const int* in_sizes, int n_in,
                              void* d_out, int out_size) {
    const float* x     = (const float*)d_in[0];
    const float* loss  = (const float*)d_in[1];
    const float* grad  = (const float*)d_in[2];
    const float* W1    = (const float*)d_in[3];
    const float* b1    = (const float*)d_in[4];
    const float* W2    = (const float*)d_in[5];
    const float* b2    = (const float*)d_in[6];
    const float* W3    = (const float*)d_in[7];
    const float* b3    = (const float*)d_in[8];
    const float* alpha = (const float*)d_in[9];
    const int*   t_ptr = (const int*)d_in[10];
    float* out = (float*)d_out;

    float *w2r, *w3r, *h1, *h2;
    cudaGetSymbolAddress((void**)&w2r, g_W2r);
    cudaGetSymbolAddress((void**)&w3r, g_W3r);
    cudaGetSymbolAddress((void**)&h1,  g_h1);
    cudaGetSymbolAddress((void**)&h2,  g_h2);
    float* w1p;
    cudaGetSymbolAddress((void**)&w1p, g_W1p);

    cudaFuncSetAttribute(mma_gemm<0, 1>, cudaFuncAttributeMaxDynamicSharedMemorySize, SMEM_BYTES);
    cudaFuncSetAttribute(mma_gemm<0, 0>, cudaFuncAttributeMaxDynamicSharedMemorySize, SMEM_BYTES);
    cudaFuncSetAttribute(mma_gemm<1, 0>, cudaFuncAttributeMaxDynamicSharedMemorySize, SMEM_BYTES);

    // prep: tf32-RNA weights (tiny)
    {
        int n1 = KPAD1 * H1DIM;
        prep_w1<<<(n1 + 255) / 256, 256>>>(W1);
        int n2 = H1DIM * H2DIM;
        roundw_kernel<<<(n2 + 255) / 256, 256>>>(W2, w2r, n2);
        int n3 = H2DIM * DDIM;
        roundw_kernel<<<(n3 + 255) / 256, 256>>>(W3, w3r, n3);
    }

    // layer 1: (32768 x 2080) @ W1p -> relu -> h1   (A streamed from x/grad/loss)
    {
        dim3 grid(H1DIM / BN, BATCH / BM);
        mma_gemm<0, 1><<<grid, 256, SMEM_BYTES>>>(x, grad, loss, w1p, b1, h1,
                                                  BATCH, H1DIM, KPAD1, nullptr, nullptr);
    }
    // layer 2: (32768 x 512) @ W2 -> relu -> h2
    {
        dim3 grid(H2DIM / BN, BATCH / BM);
        mma_gemm<0, 0><<<grid, 256, SMEM_BYTES>>>(h1, nullptr, nullptr, w2r, b2, h2,
                                                  BATCH, H2DIM, H1DIM, nullptr, nullptr);
    }
    // layer 3: (32768 x 512) @ W3 -> scale*tanh -> out
    {
        dim3 grid(DDIM / BN, BATCH / BM);
        mma_gemm<1, 0><<<grid, 256, SMEM_BYTES>>>(h2, nullptr, nullptr, w3r, b3, out,
                                                  BATCH, DDIM, H2DIM, alpha, t_ptr);
    }
}